// round 6
// baseline (speedup 1.0000x reference)
#include <cuda_runtime.h>
#include <cstddef>
#include <cstdint>

#define NSEL      20000
#define NB        32      // batch rows
#define IP        128     // in planes (K)
#define OP        32      // hidden planes (N)
#define CK        32      // K-chunk (floats)
#define XP        36      // xs row pitch -> conflict-free A frags
#define WP        40      // ws row pitch -> conflict-free B frags
#define NTHREADS  128

__device__ __forceinline__ uint32_t smem_u32(const void* p) {
    uint32_t a;
    asm("{ .reg .u64 t; cvta.to.shared.u64 t, %1; cvt.u32.u64 %0, t; }"
        : "=r"(a) : "l"(p));
    return a;
}
__device__ __forceinline__ void cp_async16(uint32_t dst, const void* src) {
    asm volatile("cp.async.cg.shared.global [%0], [%1], 16;\n" :: "r"(dst), "l"(src));
}
__device__ __forceinline__ void cp_async_commit() {
    asm volatile("cp.async.commit_group;\n" ::: "memory");
}
template <int N>
__device__ __forceinline__ void cp_async_wait() {
    asm volatile("cp.async.wait_group %0;\n" :: "n"(N) : "memory");
}
__device__ __forceinline__ void mma_tf32(float* d, const uint32_t* a,
                                         uint32_t b0, uint32_t b1) {
    asm("mma.sync.aligned.m16n8k8.row.col.f32.tf32.tf32.f32 "
        "{%0,%1,%2,%3}, {%4,%5,%6,%7}, {%8,%9}, {%0,%1,%2,%3};"
        : "+f"(d[0]), "+f"(d[1]), "+f"(d[2]), "+f"(d[3])
        : "r"(a[0]), "r"(a[1]), "r"(a[2]), "r"(a[3]), "r"(b0), "r"(b1));
}

__global__ __launch_bounds__(NTHREADS, 9)
void voxel_mlp_kernel(
    const float* __restrict__ x,       // [32, 20000, 128]
    const int*   __restrict__ vidx,    // [20000]
    const float* __restrict__ w0,      // [40000, 128, 32]
    const float* __restrict__ b0,      // [40000, 32]
    const float* __restrict__ w1,      // [40000, 32]
    const float* __restrict__ b1,      // [40000]
    float*       __restrict__ out)     // [32, 20000]
{
    __shared__ float xs[2][NB * XP];       // 9.2 KB
    __shared__ float ws[2][CK * WP];       // 10.2 KB
    __shared__ float b0s[2][OP];
    __shared__ float w1s[2][OP];
    __shared__ float b1s[2];
    __shared__ float pwork[2][2][NB];      // [param parity][n-half][row]

    const int bid = blockIdx.x;
    const int t   = threadIdx.x;
    const int G   = gridDim.x;

    int n_cur = bid;
    if (n_cur >= NSEL) return;

    const uint32_t xs_base = smem_u32(xs);
    const uint32_t ws_base = smem_u32(ws);

    // stage one K-chunk of (x tile, w0 tile) for voxel n/vi into buffer `buf`
    auto load_chunk = [&](int n, int vi, int c, int buf) {
        const float4* gx = (const float4*)x;
        const float4* gw = (const float4*)w0 + (size_t)vi * (IP * OP / 4);
        #pragma unroll
        for (int s = 0; s < 2; ++s) {
            int q  = t + NTHREADS * s;        // 0..255
            int b  = q >> 3;                  // batch row 0..31
            int f4 = q & 7;
            cp_async16(xs_base + (uint32_t)(buf * NB * XP + b * XP + 4 * f4) * 4,
                       gx + (size_t)(b * NSEL + n) * (IP / 4) + c * (CK / 4) + f4);
        }
        #pragma unroll
        for (int s = 0; s < 2; ++s) {
            int q  = t + NTHREADS * s;        // 0..255
            int kr = q >> 3;
            int f4 = q & 7;
            cp_async16(ws_base + (uint32_t)(buf * CK * WP + kr * WP + 4 * f4) * 4,
                       gw + c * (CK * OP / 4) + q);
        }
        cp_async_commit();
    };

    auto load_params = [&](int vi, int par) {
        if (t < OP) {
            b0s[par][t] = b0[(size_t)vi * OP + t];
            w1s[par][t] = w1[(size_t)vi * OP + t];
        }
        if (t == 0) b1s[par] = b1[vi];
    };

    // warp tiling: 4 warps -> (m 2) x (n 2), each warp m16 x n16
    const int wid   = t >> 5;
    const int lane  = t & 31;
    const int g     = lane >> 2;
    const int tc    = lane & 3;
    const int m_off = (wid & 1) * 16;
    const int n_off = (wid >> 1) * 16;
    const int nhalf = wid >> 1;

    const uint32_t HIMASK = 0xFFFFE000u;
    const float inv128 = 0.0078125f;
    const float inv32  = 0.03125f;

    float acc[2][4];
    #pragma unroll
    for (int ti = 0; ti < 2; ++ti)
        #pragma unroll
        for (int r = 0; r < 4; ++r) acc[ti][r] = 0.f;

    // ---- pipeline prologue: voxel 0's chunks 0,1 + params ----
    int vi_cur = __ldg(vidx + n_cur);
    load_chunk(n_cur, vi_cur, 0, 0);
    load_params(vi_cur, 0);
    load_chunk(n_cur, vi_cur, 1, 1);

    for (int v = 0; ; ++v) {
        const int  par   = v & 1;
        const int  n_nxt = n_cur + G;
        const bool hn    = (n_nxt < NSEL);
        const int  vi_nxt = hn ? __ldg(vidx + n_nxt) : 0;

        #pragma unroll
        for (int ch = 0; ch < 4; ++ch) {
            // pending groups: {c, c+1?}; c+1 exists iff ch<3 || hn
            if ((ch < 3) || hn) cp_async_wait<1>();
            else                cp_async_wait<0>();
            __syncthreads();

            const int   buf = ch & 1;
            const float* xb = &xs[buf][0];
            const float* wb = &ws[buf][0];

            #pragma unroll
            for (int ks = 0; ks < CK / 8; ++ks) {
                const int kk = ks * 8;

                float af[4];
                af[0] = xb[(m_off + g)     * XP + kk + tc];
                af[1] = xb[(m_off + g + 8) * XP + kk + tc];
                af[2] = xb[(m_off + g)     * XP + kk + tc + 4];
                af[3] = xb[(m_off + g + 8) * XP + kk + tc + 4];

                uint32_t ah[4], al[4];
                #pragma unroll
                for (int r = 0; r < 4; ++r) {
                    ah[r] = __float_as_uint(af[r]) & HIMASK;
                    al[r] = __float_as_uint(af[r] - __uint_as_float(ah[r]));
                }

                #pragma unroll
                for (int ti = 0; ti < 2; ++ti) {
                    const int nb = n_off + 8 * ti + g;
                    float bf0 = wb[(kk + tc)     * WP + nb];
                    float bf1 = wb[(kk + tc + 4) * WP + nb];
                    uint32_t bh0 = __float_as_uint(bf0) & HIMASK;
                    uint32_t bl0 = __float_as_uint(bf0 - __uint_as_float(bh0));
                    uint32_t bh1 = __float_as_uint(bf1) & HIMASK;
                    uint32_t bl1 = __float_as_uint(bf1 - __uint_as_float(bh1));

                    mma_tf32(acc[ti], ah, bh0, bh1);
                    mma_tf32(acc[ti], al, bh0, bh1);
                    mma_tf32(acc[ti], ah, bl0, bl1);
                }
            }
            __syncthreads();   // all reads of buf done before refill

            // issue chunk c+2 (same buffer we just finished reading)
            if (ch < 2) {
                load_chunk(n_cur, vi_cur, ch + 2, buf);
            } else if (hn) {
                load_chunk(n_nxt, vi_nxt, ch - 2, buf);
                if (ch == 2) load_params(vi_nxt, par ^ 1);
            }
        }

        // ---- epilogue for voxel v: GELU + layer-1 projection ----
        {
            float pr[2] = {0.f, 0.f};
            #pragma unroll
            for (int ti = 0; ti < 2; ++ti) {
                const int c0 = n_off + 8 * ti + 2 * tc;
                #pragma unroll
                for (int r = 0; r < 4; ++r) {
                    const int o = c0 + (r & 1);
                    float vv = acc[ti][r] * inv128 + b0s[par][o];
                    float ge = 0.5f * vv * (1.f + erff(vv * 0.70710678118654752f));
                    pr[r >> 1] = fmaf(ge, w1s[par][o], pr[r >> 1]);
                }
            }
            #pragma unroll
            for (int off = 1; off < 4; off <<= 1) {
                pr[0] += __shfl_xor_sync(0xffffffffu, pr[0], off);
                pr[1] += __shfl_xor_sync(0xffffffffu, pr[1], off);
            }
            if (tc == 0) {
                pwork[par][nhalf][m_off + g]     = pr[0];
                pwork[par][nhalf][m_off + g + 8] = pr[1];
            }
            __syncthreads();
            if (t < NB)
                out[(size_t)t * NSEL + n_cur] =
                    (pwork[par][0][t] + pwork[par][1][t]) * inv32 + b1s[par];

            #pragma unroll
            for (int ti = 0; ti < 2; ++ti)
                #pragma unroll
                for (int r = 0; r < 4; ++r) acc[ti][r] = 0.f;
        }

        if (!hn) break;
        n_cur  = n_nxt;
        vi_cur = vi_nxt;
    }
}

extern "C" void kernel_launch(void* const* d_in, const int* in_sizes, int n_in,
                              void* d_out, int out_size)
{
    const float* x    = (const float*)d_in[0];
    const int*   vidx = (const int*)  d_in[1];
    const float* w0   = (const float*)d_in[2];
    const float* b0   = (const float*)d_in[3];
    const float* w1   = (const float*)d_in[4];
    const float* b1   = (const float*)d_in[5];
    float* out = (float*)d_out;

    int dev = 0;
    cudaGetDevice(&dev);
    int sm = 148;
    cudaDeviceGetAttribute(&sm, cudaDevAttrMultiProcessorCount, dev);
    int bpm = 1;
    cudaOccupancyMaxActiveBlocksPerMultiprocessor(&bpm, voxel_mlp_kernel,
                                                  NTHREADS, 0);
    if (bpm < 1) bpm = 1;
    int grid = sm * bpm;
    if (grid > NSEL) grid = NSEL;

    voxel_mlp_kernel<<<grid, NTHREADS>>>(x, vidx, w0, b0, w1, b1, out);
}

// round 7
// speedup vs baseline: 1.1151x; 1.1151x over previous
#include <cuda_runtime.h>
#include <cstddef>
#include <cstdint>

#define NSEL      20000
#define NB        32      // batch rows
#define IP        128     // in planes (K)
#define OP        32      // hidden planes (N)
#define CK        32      // K-chunk (floats)
#define XP        36      // xs row pitch -> conflict-free A frags
#define WP        40      // ws row pitch -> conflict-free B frags
#define NTHREADS  128
#define VPC       2       // voxels per CTA

__device__ __forceinline__ uint32_t smem_u32(const void* p) {
    uint32_t a;
    asm("{ .reg .u64 t; cvta.to.shared.u64 t, %1; cvt.u32.u64 %0, t; }"
        : "=r"(a) : "l"(p));
    return a;
}
__device__ __forceinline__ void cp_async16(uint32_t dst, const void* src) {
    asm volatile("cp.async.cg.shared.global [%0], [%1], 16;\n" :: "r"(dst), "l"(src));
}
__device__ __forceinline__ void cp_async_commit() {
    asm volatile("cp.async.commit_group;\n" ::: "memory");
}
template <int N>
__device__ __forceinline__ void cp_async_wait() {
    asm volatile("cp.async.wait_group %0;\n" :: "n"(N) : "memory");
}
__device__ __forceinline__ void mma_tf32(float* d, const uint32_t* a,
                                         uint32_t b0, uint32_t b1) {
    asm("mma.sync.aligned.m16n8k8.row.col.f32.tf32.tf32.f32 "
        "{%0,%1,%2,%3}, {%4,%5,%6,%7}, {%8,%9}, {%0,%1,%2,%3};"
        : "+f"(d[0]), "+f"(d[1]), "+f"(d[2]), "+f"(d[3])
        : "r"(a[0]), "r"(a[1]), "r"(a[2]), "r"(a[3]), "r"(b0), "r"(b1));
}

__global__ __launch_bounds__(NTHREADS, 10)
void voxel_mlp_kernel(
    const float* __restrict__ x,       // [32, 20000, 128]
    const int*   __restrict__ vidx,    // [20000]
    const float* __restrict__ w0,      // [40000, 128, 32]
    const float* __restrict__ b0,      // [40000, 32]
    const float* __restrict__ w1,      // [40000, 32]
    const float* __restrict__ b1,      // [40000]
    float*       __restrict__ out)     // [32, 20000]
{
    __shared__ float xs[2][NB * XP];       // 9.2 KB
    __shared__ float ws[2][CK * WP];       // 10.2 KB
    __shared__ float b0s[2][OP];
    __shared__ float w1s[2][OP];
    __shared__ float b1s[2];
    __shared__ float pwork[2][2][NB];      // [parity][n-half][row]

    const int bid = blockIdx.x;
    const int t   = threadIdx.x;
    const int G   = NSEL / VPC;            // 10000 (voxel stride)

    int n_cur = bid;

    const uint32_t xs_base = smem_u32(xs);
    const uint32_t ws_base = smem_u32(ws);

    auto load_chunk = [&](int n, int vi, int c, int buf) {
        const float4* gx = (const float4*)x;
        const float4* gw = (const float4*)w0 + (size_t)vi * (IP * OP / 4);
        #pragma unroll
        for (int s = 0; s < 2; ++s) {
            int q  = t + NTHREADS * s;        // 0..255
            int b  = q >> 3;                  // batch row 0..31
            int f4 = q & 7;
            cp_async16(xs_base + (uint32_t)(buf * NB * XP + b * XP + 4 * f4) * 4,
                       gx + (size_t)(b * NSEL + n) * (IP / 4) + c * (CK / 4) + f4);
        }
        #pragma unroll
        for (int s = 0; s < 2; ++s) {
            int q  = t + NTHREADS * s;        // 0..255
            int kr = q >> 3;
            int f4 = q & 7;
            cp_async16(ws_base + (uint32_t)(buf * CK * WP + kr * WP + 4 * f4) * 4,
                       gw + c * (CK * OP / 4) + q);
        }
        cp_async_commit();
    };

    auto load_params = [&](int vi, int par) {
        if (t < OP) {
            b0s[par][t] = b0[(size_t)vi * OP + t];
            w1s[par][t] = w1[(size_t)vi * OP + t];
        }
        if (t == 0) b1s[par] = b1[vi];
    };

    // warp tiling: 4 warps -> (m 2) x (n 2), each warp m16 x n16
    const int wid   = t >> 5;
    const int lane  = t & 31;
    const int g     = lane >> 2;
    const int tc    = lane & 3;
    const int m_off = (wid & 1) * 16;
    const int n_off = (wid >> 1) * 16;
    const int nhalf = wid >> 1;

    const uint32_t HIMASK = 0xFFFFE000u;
    const float inv128 = 0.0078125f;
    const float inv32  = 0.03125f;

    float acc[2][4];
    #pragma unroll
    for (int ti = 0; ti < 2; ++ti)
        #pragma unroll
        for (int r = 0; r < 4; ++r) acc[ti][r] = 0.f;

    // ---- prologue: voxel 0's chunks 0,1 + params ----
    int vi_cur = __ldg(vidx + n_cur);
    load_chunk(n_cur, vi_cur, 0, 0);
    load_params(vi_cur, 0);
    load_chunk(n_cur, vi_cur, 1, 1);

    #pragma unroll
    for (int v = 0; v < VPC; ++v) {
        const int  par    = v & 1;
        const bool hn     = (v + 1 < VPC);
        const int  n_nxt  = n_cur + G;
        const int  vi_nxt = hn ? __ldg(vidx + n_nxt) : 0;

        #pragma unroll
        for (int ch = 0; ch < 4; ++ch) {
            if ((ch < 3) || hn) cp_async_wait<1>();
            else                cp_async_wait<0>();
            __syncthreads();

            const int   buf = ch & 1;
            const float* xb = &xs[buf][0];
            const float* wb = &ws[buf][0];

            #pragma unroll
            for (int ks = 0; ks < CK / 8; ++ks) {
                const int kk = ks * 8;

                float af[4];
                af[0] = xb[(m_off + g)     * XP + kk + tc];
                af[1] = xb[(m_off + g + 8) * XP + kk + tc];
                af[2] = xb[(m_off + g)     * XP + kk + tc + 4];
                af[3] = xb[(m_off + g + 8) * XP + kk + tc + 4];

                uint32_t ah[4], al[4];
                #pragma unroll
                for (int r = 0; r < 4; ++r) {
                    ah[r] = __float_as_uint(af[r]) & HIMASK;
                    al[r] = __float_as_uint(af[r] - __uint_as_float(ah[r]));
                }

                #pragma unroll
                for (int ti = 0; ti < 2; ++ti) {
                    const int nb = n_off + 8 * ti + g;
                    float bf0 = wb[(kk + tc)     * WP + nb];
                    float bf1 = wb[(kk + tc + 4) * WP + nb];
                    uint32_t bh0 = __float_as_uint(bf0) & HIMASK;
                    uint32_t bl0 = __float_as_uint(bf0 - __uint_as_float(bh0));
                    uint32_t bh1 = __float_as_uint(bf1) & HIMASK;
                    uint32_t bl1 = __float_as_uint(bf1 - __uint_as_float(bh1));

                    mma_tf32(acc[ti], ah, bh0, bh1);
                    mma_tf32(acc[ti], al, bh0, bh1);
                    mma_tf32(acc[ti], ah, bl0, bl1);
                }
            }
            __syncthreads();   // all reads of buf done before refill

            if (ch < 2) {
                load_chunk(n_cur, vi_cur, ch + 2, buf);
            } else if (hn) {
                load_chunk(n_nxt, vi_nxt, ch - 2, buf);
                if (ch == 2) load_params(vi_nxt, par ^ 1);
            }
        }

        // ---- epilogue: GELU + layer-1 projection (loads may be in flight) ----
        {
            float pr[2] = {0.f, 0.f};
            #pragma unroll
            for (int ti = 0; ti < 2; ++ti) {
                const int c0 = n_off + 8 * ti + 2 * tc;
                #pragma unroll
                for (int r = 0; r < 4; ++r) {
                    const int o = c0 + (r & 1);
                    float vv = acc[ti][r] * inv128 + b0s[par][o];
                    float ge = 0.5f * vv * (1.f + erff(vv * 0.70710678118654752f));
                    pr[r >> 1] = fmaf(ge, w1s[par][o], pr[r >> 1]);
                }
            }
            #pragma unroll
            for (int off = 1; off < 4; off <<= 1) {
                pr[0] += __shfl_xor_sync(0xffffffffu, pr[0], off);
                pr[1] += __shfl_xor_sync(0xffffffffu, pr[1], off);
            }
            if (tc == 0) {
                pwork[par][nhalf][m_off + g]     = pr[0];
                pwork[par][nhalf][m_off + g + 8] = pr[1];
            }
            __syncthreads();
            if (t < NB)
                out[(size_t)t * NSEL + n_cur] =
                    (pwork[par][0][t] + pwork[par][1][t]) * inv32 + b1s[par];

            #pragma unroll
            for (int ti = 0; ti < 2; ++ti)
                #pragma unroll
                for (int r = 0; r < 4; ++r) acc[ti][r] = 0.f;
        }

        n_cur  = n_nxt;
        vi_cur = vi_nxt;
    }
}

extern "C" void kernel_launch(void* const* d_in, const int* in_sizes, int n_in,
                              void* d_out, int out_size)
{
    const float* x    = (const float*)d_in[0];
    const int*   vidx = (const int*)  d_in[1];
    const float* w0   = (const float*)d_in[2];
    const float* b0   = (const float*)d_in[3];
    const float* w1   = (const float*)d_in[4];
    const float* b1   = (const float*)d_in[5];
    float* out = (float*)d_out;

    voxel_mlp_kernel<<<NSEL / VPC, NTHREADS>>>(x, vidx, w0, b0, w1, b1, out);
}

// round 8
// speedup vs baseline: 1.1223x; 1.0065x over previous
#include <cuda_runtime.h>
#include <cstddef>
#include <cstdint>

#define NSEL      20000
#define NB        32      // batch rows
#define IP        128     // in planes (K)
#define OP        32      // hidden planes (N)
#define CK        32      // K-chunk (floats)
#define XP        36      // xs row pitch -> conflict-free A frags
#define WP        40      // ws row pitch -> conflict-free B frags
#define NTHREADS  128
#define VPC       2       // voxels per CTA
#define NCH       (VPC * IP / CK)   // 8 chunks per CTA

__device__ __forceinline__ uint32_t smem_u32(const void* p) {
    uint32_t a;
    asm("{ .reg .u64 t; cvta.to.shared.u64 t, %1; cvt.u32.u64 %0, t; }"
        : "=r"(a) : "l"(p));
    return a;
}
__device__ __forceinline__ void cp_async16(uint32_t dst, const void* src) {
    asm volatile("cp.async.cg.shared.global [%0], [%1], 16;\n" :: "r"(dst), "l"(src));
}
__device__ __forceinline__ void cp_async_commit() {
    asm volatile("cp.async.commit_group;\n" ::: "memory");
}
template <int N>
__device__ __forceinline__ void cp_async_wait() {
    asm volatile("cp.async.wait_group %0;\n" :: "n"(N) : "memory");
}
__device__ __forceinline__ void mma_tf32(float* d, const uint32_t* a,
                                         uint32_t b0, uint32_t b1) {
    asm("mma.sync.aligned.m16n8k8.row.col.f32.tf32.tf32.f32 "
        "{%0,%1,%2,%3}, {%4,%5,%6,%7}, {%8,%9}, {%0,%1,%2,%3};"
        : "+f"(d[0]), "+f"(d[1]), "+f"(d[2]), "+f"(d[3])
        : "r"(a[0]), "r"(a[1]), "r"(a[2]), "r"(a[3]), "r"(b0), "r"(b1));
}

__global__ __launch_bounds__(NTHREADS, 7)
void voxel_mlp_kernel(
    const float* __restrict__ x,       // [32, 20000, 128]
    const int*   __restrict__ vidx,    // [20000]
    const float* __restrict__ w0,      // [40000, 128, 32]
    const float* __restrict__ b0,      // [40000, 32]
    const float* __restrict__ w1,      // [40000, 32]
    const float* __restrict__ b1,      // [40000]
    float*       __restrict__ out)     // [32, 20000]
{
    __shared__ float xs[3][NB * XP];       // 13.8 KB
    __shared__ float ws[3][CK * WP];       // 15.4 KB
    __shared__ float b0s[2][OP];
    __shared__ float w1s[2][OP];
    __shared__ float b1s[2];
    __shared__ float pwork[2][2][NB];

    const int bid = blockIdx.x;
    const int t   = threadIdx.x;

    const int n0 = bid;                // voxel 0
    const int n1 = bid + NSEL / VPC;   // voxel 1 (always < NSEL)
    const int vi0 = __ldg(vidx + n0);
    const int vi1 = __ldg(vidx + n1);

    const uint32_t xs_base = smem_u32(xs);
    const uint32_t ws_base = smem_u32(ws);

    auto load_chunk = [&](int n, int vi, int c, int buf) {
        const float4* gx = (const float4*)x;
        const float4* gw = (const float4*)w0 + (size_t)vi * (IP * OP / 4);
        #pragma unroll
        for (int s = 0; s < 2; ++s) {
            int q  = t + NTHREADS * s;        // 0..255
            int b  = q >> 3;                  // batch row 0..31
            int f4 = q & 7;
            cp_async16(xs_base + (uint32_t)(buf * NB * XP + b * XP + 4 * f4) * 4,
                       gx + (size_t)(b * NSEL + n) * (IP / 4) + c * (CK / 4) + f4);
        }
        #pragma unroll
        for (int s = 0; s < 2; ++s) {
            int q  = t + NTHREADS * s;        // 0..255
            int kr = q >> 3;
            int f4 = q & 7;
            cp_async16(ws_base + (uint32_t)(buf * CK * WP + kr * WP + 4 * f4) * 4,
                       gw + c * (CK * OP / 4) + q);
        }
        cp_async_commit();
    };

    auto load_params = [&](int vi, int par) {
        if (t < OP) {
            b0s[par][t] = b0[(size_t)vi * OP + t];
            w1s[par][t] = w1[(size_t)vi * OP + t];
        }
        if (t == 0) b1s[par] = b1[vi];
    };

    // warp tiling: 4 warps -> (m 2) x (n 2), each warp m16 x n16
    const int wid   = t >> 5;
    const int lane  = t & 31;
    const int g     = lane >> 2;
    const int tc    = lane & 3;
    const int m_off = (wid & 1) * 16;
    const int n_off = (wid >> 1) * 16;
    const int nhalf = wid >> 1;

    const uint32_t HIMASK = 0xFFFFE000u;
    const float inv128 = 0.0078125f;
    const float inv32  = 0.03125f;

    float acc[2][4];
    #pragma unroll
    for (int ti = 0; ti < 2; ++ti)
        #pragma unroll
        for (int r = 0; r < 4; ++r) acc[ti][r] = 0.f;

    // ---- prologue: 3 chunks deep ----
    load_chunk(n0, vi0, 0, 0);
    load_params(vi0, 0);
    load_chunk(n0, vi0, 1, 1);
    load_chunk(n0, vi0, 2, 2);

    #pragma unroll
    for (int q = 0; q < NCH; ++q) {
        // chunk q must be complete; allow up to 2 younger groups pending
        if (q < NCH - 2)      cp_async_wait<2>();
        else if (q == NCH - 2) cp_async_wait<1>();
        else                   cp_async_wait<0>();
        __syncthreads();

        const int   buf = q % 3;
        const float* xb = &xs[buf][0];
        const float* wb = &ws[buf][0];

        #pragma unroll
        for (int ks = 0; ks < CK / 8; ++ks) {
            const int kk = ks * 8;

            float af[4];
            af[0] = xb[(m_off + g)     * XP + kk + tc];
            af[1] = xb[(m_off + g + 8) * XP + kk + tc];
            af[2] = xb[(m_off + g)     * XP + kk + tc + 4];
            af[3] = xb[(m_off + g + 8) * XP + kk + tc + 4];

            uint32_t ah[4], al[4];
            #pragma unroll
            for (int r = 0; r < 4; ++r) {
                ah[r] = __float_as_uint(af[r]) & HIMASK;
                al[r] = __float_as_uint(af[r] - __uint_as_float(ah[r]));
            }

            #pragma unroll
            for (int ti = 0; ti < 2; ++ti) {
                const int nb = n_off + 8 * ti + g;
                float bf0 = wb[(kk + tc)     * WP + nb];
                float bf1 = wb[(kk + tc + 4) * WP + nb];
                uint32_t bh0 = __float_as_uint(bf0) & HIMASK;
                uint32_t bl0 = __float_as_uint(bf0 - __uint_as_float(bh0));
                uint32_t bh1 = __float_as_uint(bf1) & HIMASK;
                uint32_t bl1 = __float_as_uint(bf1 - __uint_as_float(bh1));

                mma_tf32(acc[ti], ah, bh0, bh1);
                mma_tf32(acc[ti], al, bh0, bh1);
                mma_tf32(acc[ti], ah, bl0, bl1);
            }
        }
        __syncthreads();   // all reads of buf done before refill

        // issue chunk q+3 into the buffer just freed
        if (q + 3 < NCH) {
            const int qq = q + 3;
            const int vv = qq >> 2;        // voxel of chunk qq
            load_chunk(vv ? n1 : n0, vv ? vi1 : vi0, qq & 3, qq % 3);
            if (q == 1) load_params(vi1, 1);
        }

        // ---- per-voxel epilogue after its last chunk ----
        if ((q & 3) == 3) {
            const int par = q >> 2;
            const int nn  = par ? n1 : n0;

            float pr[2] = {0.f, 0.f};
            #pragma unroll
            for (int ti = 0; ti < 2; ++ti) {
                const int c0 = n_off + 8 * ti + 2 * tc;
                #pragma unroll
                for (int r = 0; r < 4; ++r) {
                    const int o = c0 + (r & 1);
                    float vv = acc[ti][r] * inv128 + b0s[par][o];
                    float ge = 0.5f * vv * (1.f + erff(vv * 0.70710678118654752f));
                    pr[r >> 1] = fmaf(ge, w1s[par][o], pr[r >> 1]);
                }
            }
            #pragma unroll
            for (int off = 1; off < 4; off <<= 1) {
                pr[0] += __shfl_xor_sync(0xffffffffu, pr[0], off);
                pr[1] += __shfl_xor_sync(0xffffffffu, pr[1], off);
            }
            if (tc == 0) {
                pwork[par][nhalf][m_off + g]     = pr[0];
                pwork[par][nhalf][m_off + g + 8] = pr[1];
            }
            __syncthreads();
            if (t < NB)
                out[(size_t)t * NSEL + nn] =
                    (pwork[par][0][t] + pwork[par][1][t]) * inv32 + b1s[par];

            #pragma unroll
            for (int ti = 0; ti < 2; ++ti)
                #pragma unroll
                for (int r = 0; r < 4; ++r) acc[ti][r] = 0.f;
        }
    }
}

extern "C" void kernel_launch(void* const* d_in, const int* in_sizes, int n_in,
                              void* d_out, int out_size)
{
    const float* x    = (const float*)d_in[0];
    const int*   vidx = (const int*)  d_in[1];
    const float* w0   = (const float*)d_in[2];
    const float* b0   = (const float*)d_in[3];
    const float* w1   = (const float*)d_in[4];
    const float* b1   = (const float*)d_in[5];
    float* out = (float*)d_out;

    voxel_mlp_kernel<<<NSEL / VPC, NTHREADS>>>(x, vidx, w0, b0, w1, b1, out);
}